// round 6
// baseline (speedup 1.0000x reference)
#include <cuda_runtime.h>
#include <cuda_fp16.h>
#include <cstdint>

typedef uint32_t u32;

#define SQRTD_F 11.313708498984761f
#define BPAD 132     // float2 row stride (1056 B)

// shared memory byte offsets
#define SM_B2   0                    // B2 [128][132] float2 (hi,lo) : 135168 B
#define SM_A2   135168               // A2 [ 64][132] float2 (hi,lo) :  67584 B
#define SM_MISC 202752
#define SMEM_BYTES 205504

static __device__ __forceinline__ float tf32_rna(float f) {
    u32 u;
    asm("cvt.rna.tf32.f32 %0, %1;" : "=r"(u) : "f"(f));
    return __uint_as_float(u);
}
static __device__ __forceinline__ u32 fb(float f) { return __float_as_uint(f); }

static __device__ __forceinline__ void mma8(float c[4], u32 a0, u32 a1, u32 a2, u32 a3,
                                            u32 b0, u32 b1) {
    asm volatile(
        "mma.sync.aligned.m16n8k8.row.col.f32.tf32.tf32.f32 "
        "{%0,%1,%2,%3},{%4,%5,%6,%7},{%8,%9},{%0,%1,%2,%3};"
        : "+f"(c[0]), "+f"(c[1]), "+f"(c[2]), "+f"(c[3])
        : "r"(a0), "r"(a1), "r"(a2), "r"(a3), "r"(b0), "r"(b1));
}

// K=128 GEMM over a 16(M) x 32(N) warp tile, 3 products hh+hl+lh.
// Both operands interleaved (hi,lo) float2 in smem -> zero in-loop ALU.
static __device__ __forceinline__ void chain(const float2* __restrict__ sA2,
                                             const float2* __restrict__ sB2,
                                             float acc[4][4],
                                             int g, int t, int mrow0, int ncol0) {
    #pragma unroll 2
    for (int ks = 0; ks < 16; ks++) {
        const int k0 = ks * 8;
        u32 bh[4][2], bl[4][2];
        #pragma unroll
        for (int nt = 0; nt < 4; nt++) {
            const float2* bp = sB2 + (ncol0 + nt * 8 + g) * BPAD + k0 + t;
            float2 p0 = bp[0];
            float2 p1 = bp[4];
            bh[nt][0] = fb(p0.x); bl[nt][0] = fb(p0.y);
            bh[nt][1] = fb(p1.x); bl[nt][1] = fb(p1.y);
        }
        const float2* ap = sA2 + (mrow0 + g) * BPAD + k0 + t;
        float2 q0 = ap[0];
        float2 q1 = ap[8 * BPAD];
        float2 q2 = ap[4];
        float2 q3 = ap[8 * BPAD + 4];
        u32 ah0 = fb(q0.x), ah1 = fb(q1.x), ah2 = fb(q2.x), ah3 = fb(q3.x);
        u32 al0 = fb(q0.y), al1 = fb(q1.y), al2 = fb(q2.y), al3 = fb(q3.y);
        #pragma unroll
        for (int nt = 0; nt < 4; nt++)
            mma8(acc[nt], ah0, ah1, ah2, ah3, bh[nt][0], bh[nt][1]);
        #pragma unroll
        for (int nt = 0; nt < 4; nt++)
            mma8(acc[nt], ah0, ah1, ah2, ah3, bl[nt][0], bl[nt][1]);
        #pragma unroll
        for (int nt = 0; nt < 4; nt++)
            mma8(acc[nt], al0, al1, al2, al3, bh[nt][0], bh[nt][1]);
    }
}

__global__ __launch_bounds__(512, 1)
void tq_fused(const float* __restrict__ x, const float* __restrict__ Pi,
              const float* __restrict__ cbk, float* __restrict__ out) {
    extern __shared__ char sm[];
    float2* sB2 = (float2*)(sm + SM_B2);
    float2* sA2 = (float2*)(sm + SM_A2);
    float2* s_csd2 = (float2*)(sm + SM_MISC);          // 16 float2 (hi,lo)
    float*  s_mid  = (float*)(sm + SM_MISC + 128);     // 15 f32
    float*  s_part = (float*)(sm + SM_MISC + 192);     // 512 f32
    float*  s_cn   = (float*)(sm + SM_MISC + 2240);    // 64 f32
    float*  s_nh   = (float*)(sm + SM_MISC + 2496);    // 64 f32

    const int tid = threadIdx.x;
    const int wid = tid >> 5, lane = tid & 31;
    const int g = lane >> 2, t = lane & 3;
    const int mrow0 = (wid >> 2) * 16;      // 4 M groups
    const int ncol0 = (wid & 3) * 32;       // 4 N groups
    const int tok0 = blockIdx.x << 6;       // 64 tokens / CTA

    // Pi staging mapping (used twice): thread -> (row, 32-col segment)
    const int prow = tid >> 2, pc0 = (tid & 3) * 32;
    const float4* pr = (const float4*)(Pi + prow * 128 + pc0);

    // ---- stage B2[n][k] = (hi,lo) of Pi[n][k]  (fwd B) ----
    #pragma unroll
    for (int e = 0; e < 8; e++) {
        float4 p = pr[e];
        float h0 = tf32_rna(p.x), h1 = tf32_rna(p.y);
        float h2 = tf32_rna(p.z), h3 = tf32_rna(p.w);
        float2* bp = sB2 + prow * BPAD + pc0 + 4 * e;
        bp[0] = make_float2(h0, tf32_rna(p.x - h0));
        bp[1] = make_float2(h1, tf32_rna(p.y - h1));
        bp[2] = make_float2(h2, tf32_rna(p.z - h2));
        bp[3] = make_float2(h3, tf32_rna(p.w - h3));
    }

    // ---- load x (8 threads/token), partial sum of squares, tables ----
    const int token = tid >> 3, c0h = (tid & 7) * 16;
    float v[16];
    {
        const float4* xr = (const float4*)(x + (size_t)(tok0 + token) * 128 + c0h);
        float ss = 0.f;
        #pragma unroll
        for (int e = 0; e < 4; e++) {
            float4 p = xr[e];
            v[4 * e] = p.x; v[4 * e + 1] = p.y; v[4 * e + 2] = p.z; v[4 * e + 3] = p.w;
            ss += p.x * p.x + p.y * p.y + p.z * p.z + p.w * p.w;
        }
        s_part[tid] = ss;
    }
    if (tid < 16) {
        float c = cbk[tid];
        float a = __fdiv_rn(c, SQRTD_F);
        float h = tf32_rna(a);
        s_csd2[tid] = make_float2(h, tf32_rna(a - h));
        if (tid < 15) s_mid[tid] = (c + cbk[tid + 1]) * 0.5f;
    }
    __syncthreads();

    if (tid < 64) {
        float s = 0.f;
        #pragma unroll
        for (int e = 0; e < 8; e++) s += s_part[8 * tid + e];
        float n = __fsqrt_rn(s);
        s_cn[tid] = fmaxf(n, 1e-8f);
        s_nh[tid] = __half2float(__float2half_rn(n));
    }
    __syncthreads();

    // ---- stage A2[m][k] = (hi,lo) of x_unit[m][k] ----
    {
        const float c = s_cn[token];
        float4* ap = (float4*)(sA2 + token * BPAD + c0h);
        #pragma unroll
        for (int e = 0; e < 8; e++) {
            float u0 = __fdiv_rn(v[2 * e], c);
            float u1 = __fdiv_rn(v[2 * e + 1], c);
            float h0 = tf32_rna(u0), h1 = tf32_rna(u1);
            ap[e] = make_float4(h0, tf32_rna(u0 - h0), h1, tf32_rna(u1 - h1));
        }
    }
    __syncthreads();

    float acc[4][4];
    #pragma unroll
    for (int i = 0; i < 4; i++)
        #pragma unroll
        for (int j = 0; j < 4; j++) acc[i][j] = 0.f;

    // ---- forward: y_raw = x_unit @ Pi^T ----
    chain(sA2, sB2, acc, g, t, mrow0, ncol0);
    __syncthreads();   // all warps done reading sA2/sB2

    // ---- quantize: write (csd_hi, csd_lo) into sA2; reset acc ----
    {
        float mids[15];
        #pragma unroll
        for (int l = 0; l < 15; l++) mids[l] = s_mid[l];
        #pragma unroll
        for (int nt = 0; nt < 4; nt++) {
            #pragma unroll
            for (int r = 0; r < 4; r++) {
                float y = acc[nt][r] * SQRTD_F;
                int idx = 0;
                #pragma unroll
                for (int l = 0; l < 15; l++) idx += (y > mids[l]);
                int row = mrow0 + g + (r >> 1) * 8;
                int col = ncol0 + nt * 8 + 2 * t + (r & 1);
                sA2[row * BPAD + col] = s_csd2[idx];
                acc[nt][r] = 0.f;
            }
        }
    }

    // ---- restage B2[i][j] = (hi,lo) of Pi[j][i]  (bwd B = PiT) ----
    #pragma unroll
    for (int e = 0; e < 8; e++) {
        float4 p = pr[e];
        float pv[4] = {p.x, p.y, p.z, p.w};
        #pragma unroll
        for (int c = 0; c < 4; c++) {
            float h = tf32_rna(pv[c]);
            sB2[(pc0 + 4 * e + c) * BPAD + prow] = make_float2(h, tf32_rna(pv[c] - h));
        }
    }
    __syncthreads();

    // ---- backward: z = a_hat @ Pi ----
    chain(sA2, sB2, acc, g, t, mrow0, ncol0);

    // ---- epilogue: scale by fp16-roundtripped norm, store float2 ----
    #pragma unroll
    for (int nt = 0; nt < 4; nt++) {
        int row0 = mrow0 + g;
        int col  = ncol0 + nt * 8 + 2 * t;
        float nh0 = s_nh[row0];
        float nh1 = s_nh[row0 + 8];
        *(float2*)(out + (size_t)(tok0 + row0) * 128 + col) =
            make_float2(acc[nt][0] * nh0, acc[nt][1] * nh0);
        *(float2*)(out + (size_t)(tok0 + row0 + 8) * 128 + col) =
            make_float2(acc[nt][2] * nh1, acc[nt][3] * nh1);
    }
}

extern "C" void kernel_launch(void* const* d_in, const int* in_sizes, int n_in,
                              void* d_out, int out_size) {
    const float* x   = (const float*)d_in[0];
    const float* Pi  = (const float*)d_in[1];
    const float* cbk = (const float*)d_in[2];
    float* out = (float*)d_out;

    int ntok = in_sizes[0] / 128;
    int blocks = ntok / 64;

    cudaFuncSetAttribute(tq_fused, cudaFuncAttributeMaxDynamicSharedMemorySize, SMEM_BYTES);
    tq_fused<<<blocks, 512, SMEM_BYTES>>>(x, Pi, cbk, out);
}

// round 7
// speedup vs baseline: 1.8851x; 1.8851x over previous
#include <cuda_runtime.h>
#include <cuda_fp16.h>
#include <cstdint>

typedef uint32_t u32;

#define SQRTD_F 11.313708498984761f
#define PR 68          // u32 (fp16-pair) row stride -> (4g+t) conflict-free
#define PRB (PR * 4)   // 272 bytes

// shared memory byte offsets (each tile: 128 rows x 68 u32 = 34816 B)
#define SM_AH   0
#define SM_AL   34816
#define SM_BFH  69632
#define SM_BFL  104448
#define SM_BBH  139264
#define SM_BBL  174080
#define SM_MISC 208896
#define SMEM_BYTES 211072

static __device__ __forceinline__ u32 hpack(__half a, __half b) {
    return (u32)__half_as_ushort(a) | ((u32)__half_as_ushort(b) << 16);
}

static __device__ __forceinline__ void mma16(float c[4], u32 a0, u32 a1, u32 a2, u32 a3,
                                             u32 b0, u32 b1) {
    asm volatile(
        "mma.sync.aligned.m16n8k16.row.col.f32.f16.f16.f32 "
        "{%0,%1,%2,%3},{%4,%5,%6,%7},{%8,%9},{%0,%1,%2,%3};"
        : "+f"(c[0]), "+f"(c[1]), "+f"(c[2]), "+f"(c[3])
        : "r"(a0), "r"(a1), "r"(a2), "r"(a3), "r"(b0), "r"(b1));
}

// K=128 GEMM over a 32(M) x 64(N) warp tile using packed-fp16 hi/lo arrays.
// NP=3: hh+hl+lh.  NP=2: hh+hl (A_lo unused).
template<int NP>
static __device__ __forceinline__ void chain(const u32* __restrict__ sAh,
                                             const u32* __restrict__ sAl,
                                             const u32* __restrict__ sBh,
                                             const u32* __restrict__ sBl,
                                             float acc[2][8][4],
                                             int g, int t, int mrow0, int ncol0) {
    #pragma unroll 1
    for (int ks = 0; ks < 8; ks++) {
        const int kp = ks * 8;
        u32 bh[8][2], bl[8][2];
        #pragma unroll
        for (int nt = 0; nt < 8; nt++) {
            const int off = (ncol0 + nt * 8 + g) * PR + kp + t;
            bh[nt][0] = sBh[off];     bh[nt][1] = sBh[off + 4];
            bl[nt][0] = sBl[off];     bl[nt][1] = sBl[off + 4];
        }
        u32 ah[2][4], al[2][4];
        #pragma unroll
        for (int mt = 0; mt < 2; mt++) {
            const int off = (mrow0 + mt * 16 + g) * PR + kp + t;
            ah[mt][0] = sAh[off];            ah[mt][1] = sAh[off + 8 * PR];
            ah[mt][2] = sAh[off + 4];        ah[mt][3] = sAh[off + 8 * PR + 4];
            if (NP == 3) {
                al[mt][0] = sAl[off];        al[mt][1] = sAl[off + 8 * PR];
                al[mt][2] = sAl[off + 4];    al[mt][3] = sAl[off + 8 * PR + 4];
            }
        }
        #pragma unroll
        for (int mt = 0; mt < 2; mt++)
            #pragma unroll
            for (int nt = 0; nt < 8; nt++)
                mma16(acc[mt][nt], ah[mt][0], ah[mt][1], ah[mt][2], ah[mt][3],
                      bh[nt][0], bh[nt][1]);
        #pragma unroll
        for (int mt = 0; mt < 2; mt++)
            #pragma unroll
            for (int nt = 0; nt < 8; nt++)
                mma16(acc[mt][nt], ah[mt][0], ah[mt][1], ah[mt][2], ah[mt][3],
                      bl[nt][0], bl[nt][1]);
        if (NP == 3) {
            #pragma unroll
            for (int mt = 0; mt < 2; mt++)
                #pragma unroll
                for (int nt = 0; nt < 8; nt++)
                    mma16(acc[mt][nt], al[mt][0], al[mt][1], al[mt][2], al[mt][3],
                          bh[nt][0], bh[nt][1]);
        }
    }
}

__global__ __launch_bounds__(256, 1)
void tq_fused(const float* __restrict__ x, const float* __restrict__ Pi,
              const float* __restrict__ cbk, float* __restrict__ out) {
    extern __shared__ char sm[];
    u32* sAh  = (u32*)(sm + SM_AH);
    u32* sAl  = (u32*)(sm + SM_AL);
    u32* sBfh = (u32*)(sm + SM_BFH);
    u32* sBfl = (u32*)(sm + SM_BFL);
    u32* sBbh = (u32*)(sm + SM_BBH);
    u32* sBbl = (u32*)(sm + SM_BBL);
    __half* s_csdh = (__half*)(sm + SM_MISC);          // 16 fp16
    float*  s_mid  = (float*)(sm + SM_MISC + 64);      // 15 f32
    float*  s_part = (float*)(sm + SM_MISC + 128);     // 256 f32
    float*  s_cn   = (float*)(sm + SM_MISC + 1152);    // 128 f32
    float*  s_nh   = (float*)(sm + SM_MISC + 1664);    // 128 f32

    const int tid = threadIdx.x;
    const int wid = tid >> 5, lane = tid & 31;
    const int g = lane >> 2, t = lane & 3;
    const int mrow0 = (wid >> 1) * 32;
    const int ncol0 = (wid & 1) * 64;
    const int tok0 = blockIdx.x << 7;

    // ---- stage Bf[n][kpair] = fp16 hi/lo of Pi[n][k] (row reads) ----
    {
        const int n = tid >> 1, kh = (tid & 1) * 64;
        const float4* pr = (const float4*)(Pi + n * 128 + kh);
        #pragma unroll
        for (int e = 0; e < 16; e++) {
            float4 p = pr[e];
            __half hx = __float2half_rn(p.x), hy = __float2half_rn(p.y);
            __half hz = __float2half_rn(p.z), hw = __float2half_rn(p.w);
            int idx = n * PR + (kh >> 1) + 2 * e;
            sBfh[idx]     = hpack(hx, hy);
            sBfh[idx + 1] = hpack(hz, hw);
            sBfl[idx]     = hpack(__float2half_rn(p.x - __half2float(hx)),
                                  __float2half_rn(p.y - __half2float(hy)));
            sBfl[idx + 1] = hpack(__float2half_rn(p.z - __half2float(hz)),
                                  __float2half_rn(p.w - __half2float(hw)));
        }
    }
    // ---- stage Bb[i][jpair] = fp16 hi/lo of Pi[j][i] (column reads, L2-hot) ----
    {
        const int i = tid >> 1, jh = (tid & 1) * 64;
        #pragma unroll 4
        for (int p = 0; p < 32; p++) {
            float v0 = Pi[(jh + 2 * p) * 128 + i];
            float v1 = Pi[(jh + 2 * p + 1) * 128 + i];
            __half h0 = __float2half_rn(v0), h1 = __float2half_rn(v1);
            int idx = i * PR + (jh >> 1) + p;
            sBbh[idx] = hpack(h0, h1);
            sBbl[idx] = hpack(__float2half_rn(v0 - __half2float(h0)),
                              __float2half_rn(v1 - __half2float(h1)));
        }
    }

    // ---- load x (2 threads/token), sum of squares, tables ----
    const int token = tid >> 1, c0h = (tid & 1) * 64;
    float v[64];
    {
        const float4* xr = (const float4*)(x + (size_t)(tok0 + token) * 128 + c0h);
        float ss = 0.f;
        #pragma unroll
        for (int e = 0; e < 16; e++) {
            float4 p = xr[e];
            v[4 * e] = p.x; v[4 * e + 1] = p.y; v[4 * e + 2] = p.z; v[4 * e + 3] = p.w;
            ss += p.x * p.x + p.y * p.y + p.z * p.z + p.w * p.w;
        }
        s_part[tid] = ss;
    }
    if (tid < 16) {
        float c = cbk[tid];
        s_csdh[tid] = __float2half_rn(__fdiv_rn(c, SQRTD_F));
        if (tid < 15) s_mid[tid] = (c + cbk[tid + 1]) * 0.5f;
    }
    __syncthreads();
    if (tid < 128) {
        float s = s_part[2 * tid] + s_part[2 * tid + 1];
        float n = __fsqrt_rn(s);
        s_cn[tid] = fmaxf(n, 1e-8f);
        s_nh[tid] = __half2float(__float2half_rn(n));
    }
    __syncthreads();

    // ---- stage A[token][kpair] = fp16 hi/lo of x_unit ----
    {
        const float c = s_cn[token];
        #pragma unroll
        for (int e = 0; e < 32; e++) {
            float u0 = __fdiv_rn(v[2 * e], c);
            float u1 = __fdiv_rn(v[2 * e + 1], c);
            __half h0 = __float2half_rn(u0), h1 = __float2half_rn(u1);
            int idx = token * PR + (c0h >> 1) + e;
            sAh[idx] = hpack(h0, h1);
            sAl[idx] = hpack(__float2half_rn(u0 - __half2float(h0)),
                             __float2half_rn(u1 - __half2float(h1)));
        }
    }
    __syncthreads();

    float acc[2][8][4];
    #pragma unroll
    for (int i = 0; i < 2; i++)
        #pragma unroll
        for (int j = 0; j < 8; j++)
            #pragma unroll
            for (int k = 0; k < 4; k++) acc[i][j][k] = 0.f;

    // ---- forward: y_raw = x_unit @ Pi^T  (3-product) ----
    chain<3>(sAh, sAl, sBfh, sBfl, acc, g, t, mrow0, ncol0);
    __syncthreads();   // all warps done reading A

    // ---- quantize: y = y_raw*sqrt_d; write fp16 csd into A_hi ----
    {
        float mids[15];
        #pragma unroll
        for (int l = 0; l < 15; l++) mids[l] = s_mid[l];
        #pragma unroll
        for (int mt = 0; mt < 2; mt++) {
            #pragma unroll
            for (int nt = 0; nt < 8; nt++) {
                #pragma unroll
                for (int r = 0; r < 4; r++) {
                    float y = acc[mt][nt][r] * SQRTD_F;
                    int idx = 0;
                    #pragma unroll
                    for (int l = 0; l < 15; l++) idx += (y > mids[l]);
                    int row = mrow0 + mt * 16 + g + (r >> 1) * 8;
                    int col = ncol0 + nt * 8 + 2 * t + (r & 1);
                    *(__half*)(sm + SM_AH + row * PRB + col * 2) = s_csdh[idx];
                    acc[mt][nt][r] = 0.f;
                }
            }
        }
    }
    __syncthreads();

    // ---- backward: z = a_hat @ Pi  (2-product: a_hi * (Pi_hi + Pi_lo)) ----
    chain<2>(sAh, sAl, sBbh, sBbl, acc, g, t, mrow0, ncol0);

    // ---- epilogue: scale by fp16-roundtripped norm, store float2 ----
    #pragma unroll
    for (int mt = 0; mt < 2; mt++) {
        #pragma unroll
        for (int nt = 0; nt < 8; nt++) {
            int row0 = mrow0 + mt * 16 + g;
            int col  = ncol0 + nt * 8 + 2 * t;
            float nh0 = s_nh[row0];
            float nh1 = s_nh[row0 + 8];
            *(float2*)(out + (size_t)(tok0 + row0) * 128 + col) =
                make_float2(acc[mt][nt][0] * nh0, acc[mt][nt][1] * nh0);
            *(float2*)(out + (size_t)(tok0 + row0 + 8) * 128 + col) =
                make_float2(acc[mt][nt][2] * nh1, acc[mt][nt][3] * nh1);
        }
    }
}

extern "C" void kernel_launch(void* const* d_in, const int* in_sizes, int n_in,
                              void* d_out, int out_size) {
    const float* x   = (const float*)d_in[0];
    const float* Pi  = (const float*)d_in[1];
    const float* cbk = (const float*)d_in[2];
    float* out = (float*)d_out;

    int ntok = in_sizes[0] / 128;
    int blocks = ntok / 128;

    cudaFuncSetAttribute(tq_fused, cudaFuncAttributeMaxDynamicSharedMemorySize, SMEM_BYTES);
    tq_fused<<<blocks, 256, SMEM_BYTES>>>(x, Pi, cbk, out);
}

// round 8
// speedup vs baseline: 1.9988x; 1.0603x over previous
#include <cuda_runtime.h>
#include <cuda_fp16.h>
#include <cstdint>

typedef uint32_t u32;

#define SQRTD_F 11.313708498984761f
#define PR 68          // u32 (fp16-pair) row stride -> (4g+t) conflict-free
#define PRB (PR * 4)   // 272 bytes

// shared memory byte offsets (each tile: 128 rows x 68 u32 = 34816 B)
#define SM_AH   0
#define SM_AL   34816
#define SM_BFH  69632
#define SM_BFL  104448
#define SM_BBH  139264
#define SM_BBL  174080
#define SM_MISC 208896
#define SMEM_BYTES 212096

static __device__ __forceinline__ u32 hpack(__half a, __half b) {
    return (u32)__half_as_ushort(a) | ((u32)__half_as_ushort(b) << 16);
}

static __device__ __forceinline__ void mma16(float c[4], u32 a0, u32 a1, u32 a2, u32 a3,
                                             u32 b0, u32 b1) {
    asm volatile(
        "mma.sync.aligned.m16n8k16.row.col.f32.f16.f16.f32 "
        "{%0,%1,%2,%3},{%4,%5,%6,%7},{%8,%9},{%0,%1,%2,%3};"
        : "+f"(c[0]), "+f"(c[1]), "+f"(c[2]), "+f"(c[3])
        : "r"(a0), "r"(a1), "r"(a2), "r"(a3), "r"(b0), "r"(b1));
}

// K=128 GEMM over a 32(M) x 32(N) warp tile using packed-fp16 hi/lo arrays.
// NP=3: hh+hl+lh.  NP=2: hh+hl (A_lo unused).
template<int NP>
static __device__ __forceinline__ void chain(const u32* __restrict__ sAh,
                                             const u32* __restrict__ sAl,
                                             const u32* __restrict__ sBh,
                                             const u32* __restrict__ sBl,
                                             float acc[2][4][4],
                                             int g, int t, int mrow0, int ncol0) {
    #pragma unroll 1
    for (int ks = 0; ks < 8; ks++) {
        const int kp = ks * 8;
        u32 bh[4][2], bl[4][2];
        #pragma unroll
        for (int nt = 0; nt < 4; nt++) {
            const int off = (ncol0 + nt * 8 + g) * PR + kp + t;
            bh[nt][0] = sBh[off];     bh[nt][1] = sBh[off + 4];
            bl[nt][0] = sBl[off];     bl[nt][1] = sBl[off + 4];
        }
        u32 ah[2][4], al[2][4];
        #pragma unroll
        for (int mt = 0; mt < 2; mt++) {
            const int off = (mrow0 + mt * 16 + g) * PR + kp + t;
            ah[mt][0] = sAh[off];            ah[mt][1] = sAh[off + 8 * PR];
            ah[mt][2] = sAh[off + 4];        ah[mt][3] = sAh[off + 8 * PR + 4];
            if (NP == 3) {
                al[mt][0] = sAl[off];        al[mt][1] = sAl[off + 8 * PR];
                al[mt][2] = sAl[off + 4];    al[mt][3] = sAl[off + 8 * PR + 4];
            }
        }
        #pragma unroll
        for (int mt = 0; mt < 2; mt++)
            #pragma unroll
            for (int nt = 0; nt < 4; nt++)
                mma16(acc[mt][nt], ah[mt][0], ah[mt][1], ah[mt][2], ah[mt][3],
                      bh[nt][0], bh[nt][1]);
        #pragma unroll
        for (int mt = 0; mt < 2; mt++)
            #pragma unroll
            for (int nt = 0; nt < 4; nt++)
                mma16(acc[mt][nt], ah[mt][0], ah[mt][1], ah[mt][2], ah[mt][3],
                      bl[nt][0], bl[nt][1]);
        if (NP == 3) {
            #pragma unroll
            for (int mt = 0; mt < 2; mt++)
                #pragma unroll
                for (int nt = 0; nt < 4; nt++)
                    mma16(acc[mt][nt], al[mt][0], al[mt][1], al[mt][2], al[mt][3],
                          bh[nt][0], bh[nt][1]);
        }
    }
}

__global__ __launch_bounds__(512, 1)
void tq_fused(const float* __restrict__ x, const float* __restrict__ Pi,
              const float* __restrict__ cbk, float* __restrict__ out) {
    extern __shared__ char sm[];
    u32* sAh  = (u32*)(sm + SM_AH);
    u32* sAl  = (u32*)(sm + SM_AL);
    u32* sBfh = (u32*)(sm + SM_BFH);
    u32* sBfl = (u32*)(sm + SM_BFL);
    u32* sBbh = (u32*)(sm + SM_BBH);
    u32* sBbl = (u32*)(sm + SM_BBL);
    __half* s_csdh = (__half*)(sm + SM_MISC);          // 16 fp16
    float*  s_mid  = (float*)(sm + SM_MISC + 64);      // 15 f32
    float*  s_part = (float*)(sm + SM_MISC + 128);     // 512 f32
    float*  s_cn   = (float*)(sm + SM_MISC + 2176);    // 128 f32
    float*  s_nh   = (float*)(sm + SM_MISC + 2688);    // 128 f32

    const int tid = threadIdx.x;
    const int wid = tid >> 5, lane = tid & 31;
    const int g = lane >> 2, t = lane & 3;
    const int mrow0 = (wid >> 2) * 32;    // 4 M groups
    const int ncol0 = (wid & 3) * 32;     // 4 N groups
    const int tok0 = blockIdx.x << 7;

    // ---- stage Bf[n][kpair] = fp16 hi/lo of Pi[n][k] (row reads) ----
    {
        const int n = tid >> 2, kh = (tid & 3) * 32;
        const float4* pr = (const float4*)(Pi + n * 128 + kh);
        #pragma unroll
        for (int e = 0; e < 8; e++) {
            float4 p = pr[e];
            __half hx = __float2half_rn(p.x), hy = __float2half_rn(p.y);
            __half hz = __float2half_rn(p.z), hw = __float2half_rn(p.w);
            int idx = n * PR + (kh >> 1) + 2 * e;
            sBfh[idx]     = hpack(hx, hy);
            sBfh[idx + 1] = hpack(hz, hw);
            sBfl[idx]     = hpack(__float2half_rn(p.x - __half2float(hx)),
                                  __float2half_rn(p.y - __half2float(hy)));
            sBfl[idx + 1] = hpack(__float2half_rn(p.z - __half2float(hz)),
                                  __float2half_rn(p.w - __half2float(hw)));
        }
    }
    // ---- stage Bb[i][jpair] = fp16 hi/lo of Pi[j][i] (column reads, L2-hot) ----
    {
        const int i = tid >> 2, jh = (tid & 3) * 32;
        #pragma unroll 4
        for (int p = 0; p < 16; p++) {
            float v0 = Pi[(jh + 2 * p) * 128 + i];
            float v1 = Pi[(jh + 2 * p + 1) * 128 + i];
            __half h0 = __float2half_rn(v0), h1 = __float2half_rn(v1);
            int idx = i * PR + (jh >> 1) + p;
            sBbh[idx] = hpack(h0, h1);
            sBbl[idx] = hpack(__float2half_rn(v0 - __half2float(h0)),
                              __float2half_rn(v1 - __half2float(h1)));
        }
    }

    // ---- load x (4 threads/token), sum of squares, tables ----
    const int token = tid >> 2, c0h = (tid & 3) * 32;
    float v[32];
    {
        const float4* xr = (const float4*)(x + (size_t)(tok0 + token) * 128 + c0h);
        float ss = 0.f;
        #pragma unroll
        for (int e = 0; e < 8; e++) {
            float4 p = xr[e];
            v[4 * e] = p.x; v[4 * e + 1] = p.y; v[4 * e + 2] = p.z; v[4 * e + 3] = p.w;
            ss += p.x * p.x + p.y * p.y + p.z * p.z + p.w * p.w;
        }
        s_part[tid] = ss;
    }
    if (tid < 16) {
        float c = cbk[tid];
        s_csdh[tid] = __float2half_rn(__fdiv_rn(c, SQRTD_F));
        if (tid < 15) s_mid[tid] = (c + cbk[tid + 1]) * 0.5f;
    }
    __syncthreads();
    if (tid < 128) {
        float s = s_part[4 * tid] + s_part[4 * tid + 1]
                + s_part[4 * tid + 2] + s_part[4 * tid + 3];
        float n = __fsqrt_rn(s);
        s_cn[tid] = fmaxf(n, 1e-8f);
        s_nh[tid] = __half2float(__float2half_rn(n));
    }
    __syncthreads();

    // ---- stage A[token][kpair] = fp16 hi/lo of x_unit ----
    {
        const float c = s_cn[token];
        #pragma unroll
        for (int e = 0; e < 16; e++) {
            float u0 = __fdiv_rn(v[2 * e], c);
            float u1 = __fdiv_rn(v[2 * e + 1], c);
            __half h0 = __float2half_rn(u0), h1 = __float2half_rn(u1);
            int idx = token * PR + (c0h >> 1) + e;
            sAh[idx] = hpack(h0, h1);
            sAl[idx] = hpack(__float2half_rn(u0 - __half2float(h0)),
                             __float2half_rn(u1 - __half2float(h1)));
        }
    }
    __syncthreads();

    float acc[2][4][4];
    #pragma unroll
    for (int i = 0; i < 2; i++)
        #pragma unroll
        for (int j = 0; j < 4; j++)
            #pragma unroll
            for (int k = 0; k < 4; k++) acc[i][j][k] = 0.f;

    // ---- forward: y_raw = x_unit @ Pi^T  (3-product) ----
    chain<3>(sAh, sAl, sBfh, sBfl, acc, g, t, mrow0, ncol0);
    __syncthreads();   // all warps done reading A

    // ---- quantize: y = y_raw*sqrt_d; write fp16 csd into A_hi ----
    {
        float mids[15];
        #pragma unroll
        for (int l = 0; l < 15; l++) mids[l] = s_mid[l];
        #pragma unroll
        for (int mt = 0; mt < 2; mt++) {
            #pragma unroll
            for (int nt = 0; nt < 4; nt++) {
                #pragma unroll
                for (int r = 0; r < 4; r++) {
                    float y = acc[mt][nt][r] * SQRTD_F;
                    int idx = 0;
                    #pragma unroll
                    for (int l = 0; l < 15; l++) idx += (y > mids[l]);
                    int row = mrow0 + mt * 16 + g + (r >> 1) * 8;
                    int col = ncol0 + nt * 8 + 2 * t + (r & 1);
                    *(__half*)(sm + SM_AH + row * PRB + col * 2) = s_csdh[idx];
                    acc[mt][nt][r] = 0.f;
                }
            }
        }
    }
    __syncthreads();

    // ---- backward: z = a_hat @ Pi  (2-product: a_hi * (Pi_hi + Pi_lo)) ----
    chain<2>(sAh, sAl, sBbh, sBbl, acc, g, t, mrow0, ncol0);

    // ---- epilogue: scale by fp16-roundtripped norm, store float2 ----
    #pragma unroll
    for (int mt = 0; mt < 2; mt++) {
        #pragma unroll
        for (int nt = 0; nt < 4; nt++) {
            int row0 = mrow0 + mt * 16 + g;
            int col  = ncol0 + nt * 8 + 2 * t;
            float nh0 = s_nh[row0];
            float nh1 = s_nh[row0 + 8];
            *(float2*)(out + (size_t)(tok0 + row0) * 128 + col) =
                make_float2(acc[mt][nt][0] * nh0, acc[mt][nt][1] * nh0);
            *(float2*)(out + (size_t)(tok0 + row0 + 8) * 128 + col) =
                make_float2(acc[mt][nt][2] * nh1, acc[mt][nt][3] * nh1);
        }
    }
}

extern "C" void kernel_launch(void* const* d_in, const int* in_sizes, int n_in,
                              void* d_out, int out_size) {
    const float* x   = (const float*)d_in[0];
    const float* Pi  = (const float*)d_in[1];
    const float* cbk = (const float*)d_in[2];
    float* out = (float*)d_out;

    int ntok = in_sizes[0] / 128;
    int blocks = ntok / 128;

    cudaFuncSetAttribute(tq_fused, cudaFuncAttributeMaxDynamicSharedMemorySize, SMEM_BYTES);
    tq_fused<<<blocks, 512, SMEM_BYTES>>>(x, Pi, cbk, out);
}